// round 17
// baseline (speedup 1.0000x reference)
#include <cuda_runtime.h>
#include <cuda_fp16.h>
#include <cstdint>

#define B_  256
#define T_  1000
#define I_  64
#define H_  128
#define G_  384   // 3*H

typedef unsigned long long u64;

// ---- packed fp32x2 helpers (sm_100+) ----------------------------------------
__device__ __forceinline__ u64 fma2(u64 a, u64 b, u64 c) {
    u64 d;
    asm("fma.rn.f32x2 %0, %1, %2, %3;" : "=l"(d) : "l"(a), "l"(b), "l"(c));
    return d;
}
__device__ __forceinline__ float sum2(u64 a) {
    unsigned lo, hi;
    asm("mov.b64 {%0, %1}, %2;" : "=r"(lo), "=r"(hi) : "l"(a));
    return __uint_as_float(lo) + __uint_as_float(hi);
}
__device__ __forceinline__ u64 pack2(float x, float y) {
    u64 r;
    asm("mov.b64 %0, {%1, %2};" : "=l"(r) : "f"(x), "f"(y));
    return r;
}
__device__ __forceinline__ float tanha(float x) {
    float y;
    asm("tanh.approx.f32 %0, %1;" : "=f"(y) : "f"(x));
    return y;
}
// fp16 pair (half2 bits) -> packed fp32x2 operand
__device__ __forceinline__ u64 h2f2(unsigned h2bits) {
    __half2 h = *reinterpret_cast<__half2*>(&h2bits);
    float2 f = __half22float2(h);
    return pack2(f.x, f.y);
}

// ---------------------------------------------------------------------------
// Fused GRU: ONE kernel. 128 CTAs x 512 threads, 2 batches per CTA.
// Thread (q = t>>7, j = t&127) owns k/i-quarter q of gate rows {j,j+128,j+256},
// both batches.
//   h-dot: gates r,z weights in REGISTERS (32 u64); gate-n from SMEM
//          (paired ulonglong2, 2-deep prefetch re-primed in the epilogue
//          window) — frozen R11 structure, measured 810-812us five times.
//   x-dot: fused into the same step. Input for step s+1 is double-buffered
//          into SMEM (64 threads, LDG+STS) under the existing barriers.
//          W_ih lives in SMEM as fp16 (48KB, 6 LDS.128/thread/step);
//          x-partials for r,z accumulate into the SAME accumulators as the
//          h-dot (sigmoid(x+h) merges exactly); gate-n keeps a separate
//          x-accumulator since n = tanh(xn + r*hn).
// Partials cross the k-quarters via part[4][2][4][128]; epilogue on t<256.
// ---------------------------------------------------------------------------
__global__ __launch_bounds__(512, 1) void gru_kernel(
    const float* __restrict__ input,
    const float* __restrict__ W_ih,
    const float* __restrict__ W_hh,
    const float* __restrict__ b_ih,
    const float* __restrict__ b_hh,
    float* __restrict__ out)
{
    extern __shared__ __align__(16) char smraw[];
    ulonglong2* Wnp   = (ulonglong2*)smraw;              // [32 sid][128 j]          = 65536 B
    ulonglong2* Wih16 = (ulonglong2*)(smraw + 65536);    // [3g][4q][2h][128 j] fp16 = 49152 B
    u64*   hint  = (u64*)(smraw + 114688);               // [64 k2][2 b]             = 1024 B
    u64*   inbuf = (u64*)(smraw + 115712);               // [2 ph][32 ip][2 b]       = 1024 B
    float* part  = (float*)(smraw + 116736);             // [4][2][4][128]           = 16384 B

    const int t = threadIdx.x;
    const int j = t & 127;
    const int q = t >> 7;                                // quarter; batch for t<256
    const int b0 = blockIdx.x * 2;

    const u64* W2u = (const u64*)W_hh;                   // W_hh[g][k] as k-pairs

    // Gates r,z h-weights quarter-slices -> registers (32 u64 = 64 regs).
    u64 wreg[32];
    #pragma unroll
    for (int gi = 0; gi < 2; ++gi)
        #pragma unroll
        for (int kk = 0; kk < 16; ++kk)
            wreg[gi * 16 + kk] = W2u[(size_t)(gi * 128 + j) * 64 + q * 16 + kk];

    // Gate-n h-weights -> SMEM as paired k2: Wnp[qq*8+m][g] = {k2=qq*16+2m, +2m+1}.
    for (int idx = t; idx < 32 * 128; idx += 512) {
        int g   = idx & 127;
        int sid = idx >> 7;
        int qq  = sid >> 3, m = sid & 7;
        const u64* src = &W2u[(size_t)(2 * 128 + g) * 64 + qq * 16 + 2 * m];
        ulonglong2 v; v.x = src[0]; v.y = src[1];
        Wnp[sid * 128 + g] = v;
    }

    // W_ih -> SMEM as fp16: Wih16[(g*8 + qq*2 + hf)*128 + jj] = 4 half2
    // (i-pairs qq*8 + hf*4 + 0..3 of gate row g*128+jj).
    for (int idx = t; idx < 3072; idx += 512) {
        int jj   = idx & 127;
        int rest = idx >> 7;                 // 0..23
        int g    = rest >> 3;
        int qq   = (rest >> 1) & 3;
        int hf   = rest & 1;
        const float* src = W_ih + (size_t)(g * 128 + jj) * 64 + (qq * 8 + hf * 4) * 2;
        union { __half2 h[4]; ulonglong2 v; } u;
        #pragma unroll
        for (int w = 0; w < 4; ++w)
            u.h[w] = __floats2half2_rn(src[2 * w], src[2 * w + 1]);
        Wih16[((g * 8) + (qq * 2) + hf) * 128 + jj] = u.v;
    }

    const float bs0 = b_ih[j]       + b_hh[j];        // r: biases merge
    const float bs1 = b_ih[j + 128] + b_hh[j + 128];  // z: biases merge
    const float bhn = b_hh[j + 256];                  // n: h-side bias
    const float bin = b_ih[j + 256];                  // n: x-side bias

    if (t < 256) ((float*)hint)[t] = 0.f;
    // Prime input buffer 0 with step 0.
    if (t < 64) {
        int bb = t >> 5, ip = t & 31;
        inbuf[ip * 2 + bb] =
            *(const u64*)(input + ((size_t)(b0 + bb) * T_) * 64 + ip * 2);
    }
    float hreg = 0.f;

    const int qb = q & 1;
    float* stp = out + (size_t)(b0 + qb) * T_ * H_ + j;   // used by t<256

    const ulonglong2* hvec = (const ulonglong2*)hint;     // [k-pair] -> {b0, b1}
    const ulonglong2* wnp  = Wnp + (q * 8) * 128 + j;     // gate-n h-slice
    const ulonglong2* wih  = Wih16 + q * 256 + j;         // fp16 x-slices (+g*1024, +hf*128)
    const int hw = (j >> 1) * 4 + q * 2 + (j & 1);        // float slot of h[b=q][j]
    __syncthreads();

    // Prime the 2-deep W_n pipeline (step-invariant data).
    ulonglong2 w2a = wnp[0];
    ulonglong2 w2b = wnp[128];

    for (int step = 0; step < T_; ++step) {
        // Stage next step's input into the other phase buffer.
        if (t < 64 && step + 1 < T_) {
            int bb = t >> 5, ip = t & 31;
            u64 v = *(const u64*)(input + ((size_t)(b0 + bb) * T_ + step + 1) * 64 + ip * 2);
            inbuf[((step + 1) & 1) * 64 + ip * 2 + bb] = v;
        }

        u64 a00 = 0, a01 = 0, a10 = 0, a11 = 0, a20 = 0, a21 = 0;  // h-dots
        u64 x20 = 0, x21 = 0;                                      // gate-n x-dot

        // ---- h-dot (frozen R11 loop) ----
        #pragma unroll
        for (int m = 0; m < 8; ++m) {
            ulonglong2 h2a = hvec[q * 16 + 2 * m];       // broadcast
            ulonglong2 h2b = hvec[q * 16 + 2 * m + 1];   // broadcast
            ulonglong2 w2c = w2a;
            w2a = w2b;
            if (m < 6) w2b = wnp[(m + 2) * 128];         // distance-2 prefetch
            a00 = fma2(wreg[2 * m],          h2a.x, a00);
            a01 = fma2(wreg[2 * m],          h2a.y, a01);
            a10 = fma2(wreg[16 + 2 * m],     h2a.x, a10);
            a11 = fma2(wreg[16 + 2 * m],     h2a.y, a11);
            a20 = fma2(w2c.x,                h2a.x, a20);
            a21 = fma2(w2c.x,                h2a.y, a21);
            a00 = fma2(wreg[2 * m + 1],      h2b.x, a00);
            a01 = fma2(wreg[2 * m + 1],      h2b.y, a01);
            a10 = fma2(wreg[16 + 2 * m + 1], h2b.x, a10);
            a11 = fma2(wreg[16 + 2 * m + 1], h2b.y, a11);
            a20 = fma2(w2c.y,                h2b.x, a20);
            a21 = fma2(w2c.y,                h2b.y, a21);
        }

        // ---- fused x-dot for this step (independent of h) ----
        {
            const ulonglong2* inv = (const ulonglong2*)(inbuf + (step & 1) * 64);
            #pragma unroll
            for (int hf = 0; hf < 2; ++hf) {
                ulonglong2 vr = wih[0 * 1024 + hf * 128];   // 4 half2 each
                ulonglong2 vz = wih[1 * 1024 + hf * 128];
                ulonglong2 vn = wih[2 * 1024 + hf * 128];
                #pragma unroll
                for (int w = 0; w < 4; ++w) {
                    unsigned cr = (w < 2) ? (unsigned)(vr.x >> (32 * w))
                                          : (unsigned)(vr.y >> (32 * (w - 2)));
                    unsigned cz = (w < 2) ? (unsigned)(vz.x >> (32 * w))
                                          : (unsigned)(vz.y >> (32 * (w - 2)));
                    unsigned cn = (w < 2) ? (unsigned)(vn.x >> (32 * w))
                                          : (unsigned)(vn.y >> (32 * (w - 2)));
                    u64 wr = h2f2(cr), wz = h2f2(cz), wn = h2f2(cn);
                    ulonglong2 i2 = inv[q * 8 + hf * 4 + w];   // broadcast
                    a00 = fma2(wr, i2.x, a00);  a01 = fma2(wr, i2.y, a01);
                    a10 = fma2(wz, i2.x, a10);  a11 = fma2(wz, i2.y, a11);
                    x20 = fma2(wn, i2.x, x20);  x21 = fma2(wn, i2.y, x21);
                }
            }
        }

        // Quarter partials -> SMEM, j contiguous (1 wavefront per store).
        part[((0 * 2 + 0) * 4 + q) * 128 + j] = sum2(a00);
        part[((0 * 2 + 1) * 4 + q) * 128 + j] = sum2(a01);
        part[((1 * 2 + 0) * 4 + q) * 128 + j] = sum2(a10);
        part[((1 * 2 + 1) * 4 + q) * 128 + j] = sum2(a11);
        part[((2 * 2 + 0) * 4 + q) * 128 + j] = sum2(a20);
        part[((2 * 2 + 1) * 4 + q) * 128 + j] = sum2(a21);
        part[((3 * 2 + 0) * 4 + q) * 128 + j] = sum2(x20);
        part[((3 * 2 + 1) * 4 + q) * 128 + j] = sum2(x21);
        __syncthreads();

        // Re-prime W_n pipeline for the NEXT step NOW — overlaps the epilogue.
        w2a = wnp[0];
        w2b = wnp[128];

        if (t < 256) {                           // b = q
            const float* p0 = &part[(0 * 2 + q) * 512 + j];
            const float* p1 = &part[(1 * 2 + q) * 512 + j];
            const float* p2 = &part[(2 * 2 + q) * 512 + j];
            const float* p3 = &part[(3 * 2 + q) * 512 + j];
            float r0 = p0[0], r1 = p0[128], r2 = p0[256], r3 = p0[384];
            float z0 = p1[0], z1 = p1[128], z2 = p1[256], z3 = p1[384];
            float n0 = p2[0], n1 = p2[128], n2 = p2[256], n3 = p2[384];
            float y0 = p3[0], y1 = p3[128], y2 = p3[256], y3 = p3[384];
            const float sr = (r0 + r1) + (r2 + r3) + bs0;   // x+h merged (r)
            const float sz = (z0 + z1) + (z2 + z3) + bs1;   // x+h merged (z)
            const float hn = (n0 + n1) + (n2 + n3) + bhn;   // h-side of n
            const float xn = (y0 + y1) + (y2 + y3) + bin;   // x-side of n

            const float r = 0.5f + 0.5f * tanha(0.5f * sr);
            const float z = 0.5f + 0.5f * tanha(0.5f * sz);
            const float n = tanha(xn + r * hn);
            hreg = n + z * (hreg - n);           // (1-z)n + z*h

            ((float*)hint)[hw] = hreg;
            stp[0] = hreg;
        }
        stp += H_;
        __syncthreads();                         // h + next input visible
    }

    if (t < 256)
        out[(size_t)B_ * T_ * H_ + (size_t)(b0 + q) * H_ + j] = hreg;
}

// ---------------------------------------------------------------------------
// Launcher — single fused kernel.
// ---------------------------------------------------------------------------
extern "C" void kernel_launch(void* const* d_in, const int* in_sizes, int n_in,
                              void* d_out, int out_size)
{
    const float* input = (const float*)d_in[0];   // [B, T, I]
    const float* W_ih  = (const float*)d_in[1];   // [3H, I]
    const float* W_hh  = (const float*)d_in[2];   // [3H, H]
    const float* b_ih  = (const float*)d_in[3];   // [3H]
    const float* b_hh  = (const float*)d_in[4];   // [3H]
    float* out = (float*)d_out;

    const int gru_smem = 65536 + 49152 + 1024 + 1024 + 16384;   // 133120 B
    cudaFuncSetAttribute(gru_kernel, cudaFuncAttributeMaxDynamicSharedMemorySize,
                         gru_smem);

    gru_kernel<<<B_ / 2, 512, gru_smem>>>(input, W_ih, W_hh, b_ih, b_hh, out);
}